// round 7
// baseline (speedup 1.0000x reference)
#include <cuda_runtime.h>
#include <cooperative_groups.h>
namespace cg = cooperative_groups;

// Fixed shapes: B=32, T=1024, D=1024. All GEMM paths are dead code:
// softmax over a singleton axis => every attention weight == 1.0, so
//   context[b,d] = sum_t values[b,t,d],  aw = 1.0,  cov[b,t] = t.
#define BB 32
#define TT 1024
#define DD 1024
#define D4 256                        // float4 per row (4KB rows)
#define RANKS 8                       // CTAs per cluster = chunks per batch
#define ROWS_PER_CTA (TT / RANKS)     // 128 contiguous rows = 512KB per CTA
#define THREADS 512

// Output layout (98304 floats):
//   [0, B*D)             context
//   [B*D, B*D+B*T)       attention_weights (all 1.0)
//   [B*D+B*T, end)       coverage (cov[b,t] = t)

__global__ void __cluster_dims__(RANKS, 1, 1) __launch_bounds__(THREADS, 1)
fused_kernel(const float4* __restrict__ vals, float* __restrict__ out) {
    __shared__ float4 gather[RANKS][D4];  // 32KB: rank partials land here (rank 0 only uses all)
    __shared__ float4 laneB[D4];          // 4KB: lane-1 intra-block partial

    cg::cluster_group cl = cg::this_cluster();
    const int blk  = blockIdx.x;          // 0..255
    const int b    = blk >> 3;            // batch 0..31
    const int rank = blk & (RANKS - 1);   // 0..7 == cluster rank
    const int tid  = threadIdx.x;         // 0..511
    const int col  = tid & (D4 - 1);      // 0..255 (float4 column)
    const int lane = tid >> 8;            // 0..1

    // ---- Stream: 64 contiguous rows per lane, 8 independent loads in flight ----
    const float4* __restrict__ p =
        vals + ((size_t)b * TT + (size_t)rank * ROWS_PER_CTA + (size_t)lane * 64) * D4 + col;

    float x = 0.f, y = 0.f, z = 0.f, w = 0.f;
#pragma unroll
    for (int i = 0; i < 8; ++i) {
        float4 v0 = p[0 * (size_t)D4];
        float4 v1 = p[1 * (size_t)D4];
        float4 v2 = p[2 * (size_t)D4];
        float4 v3 = p[3 * (size_t)D4];
        float4 v4 = p[4 * (size_t)D4];
        float4 v5 = p[5 * (size_t)D4];
        float4 v6 = p[6 * (size_t)D4];
        float4 v7 = p[7 * (size_t)D4];
        p += 8 * (size_t)D4;
        x += v0.x; y += v0.y; z += v0.z; w += v0.w;
        x += v1.x; y += v1.y; z += v1.z; w += v1.w;
        x += v2.x; y += v2.y; z += v2.z; w += v2.w;
        x += v3.x; y += v3.y; z += v3.z; w += v3.w;
        x += v4.x; y += v4.y; z += v4.z; w += v4.w;
        x += v5.x; y += v5.y; z += v5.z; w += v5.w;
        x += v6.x; y += v6.y; z += v6.z; w += v6.w;
        x += v7.x; y += v7.y; z += v7.z; w += v7.w;
    }

    if (lane == 1) laneB[col] = make_float4(x, y, z, w);

    // ---- aw/cov fill: 256 blocks x 32 float4 per array, hidden in the stream ----
    if (tid >= 256 && tid < 288) {
        float4* aw4 = reinterpret_cast<float4*>(out + BB * DD);
        aw4[blk * 32 + (tid - 256)] = make_float4(1.f, 1.f, 1.f, 1.f);
    } else if (tid >= 288 && tid < 320) {
        float4* cov4 = reinterpret_cast<float4*>(out + BB * DD + BB * TT);
        const int q = blk * 32 + (tid - 288);     // float4 index into [B,T]
        const int t0 = (q * 4) & (TT - 1);
        cov4[q] = make_float4((float)t0, (float)(t0 + 1), (float)(t0 + 2), (float)(t0 + 3));
    }

    __syncthreads();

    // ---- Per-rank partial -> rank 0's smem via DSMEM (producer-pays) ----
    if (lane == 0) {
        float4 o = laneB[col];
        float4 s = make_float4(x + o.x, y + o.y, z + o.z, w + o.w);
        float4* dst = cl.map_shared_rank(&gather[rank][col], 0);
        *dst = s;                     // st.shared::cluster into rank 0's gather[rank][col]
    }

    // barrier.cluster (release/acquire): all DSMEM writes visible to rank 0
    cl.sync();

    // ---- Rank 0: fixed-order sum of 8 local smem partials -> context ----
    if (rank == 0 && tid < D4) {
        float X = 0.f, Y = 0.f, Z = 0.f, W = 0.f;
#pragma unroll
        for (int r = 0; r < RANKS; ++r) {         // fixed order -> deterministic
            float4 v = gather[r][tid];
            X += v.x; Y += v.y; Z += v.z; W += v.w;
        }
        reinterpret_cast<float4*>(out)[(size_t)b * D4 + tid] = make_float4(X, Y, Z, W);
    }
}

extern "C" void kernel_launch(void* const* d_in, const int* in_sizes, int n_in,
                              void* d_out, int out_size) {
    // Inputs: query, values, W1, b1, W2, b2, W3, b3, V, bV
    const float4* values = (const float4*)d_in[1];
    float* out = (float*)d_out;

    // 256 CTAs = 32 clusters of 8 (cluster dims baked into the kernel attribute)
    fused_kernel<<<256, THREADS>>>(values, out);
}

// round 8
// speedup vs baseline: 1.0755x; 1.0755x over previous
#include <cuda_runtime.h>

// Fixed shapes: B=32, T=1024, D=1024. All GEMM paths are dead code:
// softmax over a singleton axis => every attention weight == 1.0, so
//   context[b,d] = sum_t values[b,t,d],  aw = 1.0,  cov[b,t] = t.
#define BB 32
#define TT 1024
#define DD 1024
#define D4 256                       // float4 per row (4KB rows)
#define NCHUNK 32                    // chunks per batch
#define TC (TT / NCHUNK)             // 32 rows per chunk (128KB contiguous)

// Output layout (98304 floats):
//   [0, B*D)             context
//   [B*D, B*D+B*T)       attention_weights (all 1.0)
//   [B*D+B*T, end)       coverage (cov[b,t] = t)

__device__ float4 g_partial[BB * NCHUNK * D4];   // 4 MB scratch

// ---------------- Stage 1: streaming partial sums + aw/cov fill -------------
// The proven 6.27 TB/s shape: 1024 slim CTAs, contiguous 128KB per CTA,
// thread-per-float4-column, 8-deep load batches. __ldcs = read-once hint.
__global__ void stage1_kernel(const float4* __restrict__ vals,
                              float* __restrict__ out) {
    const int c   = blockIdx.x;      // 0..31 chunk
    const int b   = blockIdx.y;      // 0..31 batch
    const int tid = threadIdx.x;     // 0..255 (one float4 column)

    const float4* __restrict__ p = vals + ((size_t)b * TT + (size_t)c * TC) * D4 + tid;

    float x = 0.f, y = 0.f, z = 0.f, w = 0.f;
#pragma unroll
    for (int i = 0; i < TC / 8; ++i) {
        float4 v0 = __ldcs(&p[0 * (size_t)D4]);
        float4 v1 = __ldcs(&p[1 * (size_t)D4]);
        float4 v2 = __ldcs(&p[2 * (size_t)D4]);
        float4 v3 = __ldcs(&p[3 * (size_t)D4]);
        float4 v4 = __ldcs(&p[4 * (size_t)D4]);
        float4 v5 = __ldcs(&p[5 * (size_t)D4]);
        float4 v6 = __ldcs(&p[6 * (size_t)D4]);
        float4 v7 = __ldcs(&p[7 * (size_t)D4]);
        p += 8 * (size_t)D4;
        x += v0.x; y += v0.y; z += v0.z; w += v0.w;
        x += v1.x; y += v1.y; z += v1.z; w += v1.w;
        x += v2.x; y += v2.y; z += v2.z; w += v2.w;
        x += v3.x; y += v3.y; z += v3.z; w += v3.w;
        x += v4.x; y += v4.y; z += v4.z; w += v4.w;
        x += v5.x; y += v5.y; z += v5.z; w += v5.w;
        x += v6.x; y += v6.y; z += v6.z; w += v6.w;
        x += v7.x; y += v7.y; z += v7.z; w += v7.w;
    }
    g_partial[(b * NCHUNK + c) * D4 + tid] = make_float4(x, y, z, w);

    // aw/cov fill: 1024 blocks x 8 float4 per array (hidden in the stream).
    const int blk = b * NCHUNK + c;  // 0..1023
    if (tid < 8) {
        float4* aw4 = reinterpret_cast<float4*>(out + BB * DD);
        aw4[blk * 8 + tid] = make_float4(1.f, 1.f, 1.f, 1.f);
    } else if (tid >= 32 && tid < 40) {
        float4* cov4 = reinterpret_cast<float4*>(out + BB * DD + BB * TT);
        const int q = blk * 8 + (tid - 32);      // float4 index into [B,T]
        const int t0 = (q * 4) & (TT - 1);
        cov4[q] = make_float4((float)t0, (float)(t0 + 1), (float)(t0 + 2), (float)(t0 + 3));
    }
}

// ---------------- Stage 2: max-parallelism context reduce -------------------
// 1024 blocks x 256 threads = 262144 threads: ONE float4 load per thread, so
// the entire 4.2MB scratch is in flight at once (no ptxas load-serialization,
// regs stay low). Block = (d-slice of 8 float4, batch). Thread (col=tid&7,
// lane=tid>>3) loads chunk 'lane' of column 'col'; warp reads 4x128B lines.
// Then a 5-step smem tree over the 32 chunk-lanes (fixed order, deterministic).
__global__ __launch_bounds__(256) void finalize_kernel(float* __restrict__ out) {
    const int ds = blockIdx.x;       // 0..31 d-slice
    const int b  = blockIdx.y;       // 0..31 batch
    const int tid  = threadIdx.x;
    const int col  = tid & 7;        // 0..7
    const int lane = tid >> 3;       // 0..31 (chunk index)

    const int d4 = ds * 8 + col;
    float4 v = __ldcg(&g_partial[((size_t)b * NCHUNK + lane) * D4 + d4]);

    __shared__ float4 red[32][8];
    red[lane][col] = v;
    __syncthreads();

#pragma unroll
    for (int s = 16; s > 0; s >>= 1) {
        if (lane < s) {
            float4 a = red[lane][col];
            float4 c2 = red[lane + s][col];
            red[lane][col] = make_float4(a.x + c2.x, a.y + c2.y, a.z + c2.z, a.w + c2.w);
        }
        __syncthreads();
    }

    if (tid < 8) {
        reinterpret_cast<float4*>(out)[(size_t)b * D4 + ds * 8 + tid] = red[0][tid];
    }
}

extern "C" void kernel_launch(void* const* d_in, const int* in_sizes, int n_in,
                              void* d_out, int out_size) {
    // Inputs: query, values, W1, b1, W2, b2, W3, b3, V, bV
    const float4* values = (const float4*)d_in[1];
    float* out = (float*)d_out;

    dim3 grid1(NCHUNK, BB);                      // 1024 blocks
    stage1_kernel<<<grid1, D4>>>(values, out);

    dim3 grid2(32, BB);                          // 1024 blocks
    finalize_kernel<<<grid2, 256>>>(out);
}